// round 12
// baseline (speedup 1.0000x reference)
#include <cuda_runtime.h>
#include <math.h>

// ---------------- problem constants ----------------
#define NB     256                 // graphs per batch
#define G      400                 // nodes per graph
#define DEG    32                  // avg degree
#define INDIM  400
#define D1     32
#define KSEL   200                 // top-k kept nodes
#define EPG    (G*DEG)             // 12800 edges per graph
#define NN     (NB*G)              // 102400 nodes
#define ETOTLL ((long long)NB*(long long)EPG)  // 3276800 edges
#define SLOPE  0.2f
#define BN_SCL 0.99999499987f      // 1/sqrt(1+1e-5)
#define CAP    64                  // per-dst bin capacity

// output layout (float32): logits[NB*2] | pool_w[32] | sig(vals)[NB*K] | perm[NB*K]
#define OFF_POOLW (NB*2)               // 512
#define OFF_SIG   (OFF_POOLW + D1)     // 544
#define OFF_PERM  (OFF_SIG + NB*KSEL)  // 51744

// ---------------- scratch (module-static, no runtime alloc) ----------------
__device__ float g_h[(size_t)NN*D1];     // 13.1 MB
__device__ float g_out_buf[(size_t)NN*D1];
__device__ float g_as[NN];
__device__ float g_ad[NN];
__device__ float g_Whi[D1*INDIM];        // W hi, [n][k]
__device__ float g_Wlo[D1*INDIM];        // W lo, [n][k]

// ---------------- index dtype handling ----------------
__device__ __forceinline__ int detect_is64(const void* p) {
    const int* w = (const int*)p;
    int any = 0;
#pragma unroll
    for (int j = 1; j <= 15; j += 2) any |= w[j];
    return any == 0;
}
__device__ __forceinline__ int load_idx(const void* p, long long i, int is64) {
    return is64 ? (int)((const long long*)p)[i] : ((const int*)p)[i];
}

// ---------------- f32x2 / cp.async / mma helpers ----------------
typedef unsigned long long u64t;
__device__ __forceinline__ void fma2(u64t& d, u64t a, u64t b) {
    asm volatile("fma.rn.f32x2 %0, %1, %2, %0;" : "+l"(d) : "l"(a), "l"(b));
}
__device__ __forceinline__ u64t pack2(float lo, float hi) {
    u64t r;
    asm("mov.b64 %0, {%1, %2};" : "=l"(r) : "f"(lo), "f"(hi));
    return r;
}
__device__ __forceinline__ void unpack2(u64t v, float& lo, float& hi) {
    asm("mov.b64 {%0, %1}, %2;" : "=f"(lo), "=f"(hi) : "l"(v));
}
__device__ __forceinline__ void cpa16(void* s, const void* g) {
    unsigned sa = (unsigned)__cvta_generic_to_shared(s);
    asm volatile("cp.async.cg.shared.global [%0], [%1], 16;" :: "r"(sa), "l"(g));
}
__device__ __forceinline__ void cpa_commit() {
    asm volatile("cp.async.commit_group;");
}
template <int N> __device__ __forceinline__ void cpa_wait() {
    asm volatile("cp.async.wait_group %0;" :: "n"(N));
}
__device__ __forceinline__ unsigned f2tf(float f) {
    unsigned u;
    asm("cvt.rna.tf32.f32 %0, %1;" : "=r"(u) : "f"(f));
    return u;
}
__device__ __forceinline__ void mma_tf32(
    float& c0, float& c1, float& c2, float& c3,
    unsigned a0, unsigned a1, unsigned a2, unsigned a3,
    unsigned b0, unsigned b1)
{
    asm volatile(
        "mma.sync.aligned.m16n8k8.row.col.f32.tf32.tf32.f32 "
        "{%0,%1,%2,%3}, {%4,%5,%6,%7}, {%8,%9}, {%0,%1,%2,%3};"
        : "+f"(c0), "+f"(c1), "+f"(c2), "+f"(c3)
        : "r"(a0), "r"(a1), "r"(a2), "r"(a3), "r"(b0), "r"(b1));
}

// ============================================================================
// K0: split W into TF32 hi/lo, transposed to [n][k].
// ============================================================================
__global__ __launch_bounds__(256) void k_prep(const float* __restrict__ W)
{
    int i = blockIdx.x * 256 + threadIdx.x;    // i = k*32 + n
    if (i < INDIM * D1) {
        int k = i >> 5, n = i & 31;
        float f = W[i];
        unsigned hi = f2tf(f);
        g_Whi[n * INDIM + k] = __uint_as_float(hi);
        g_Wlo[n * INDIM + k] = __uint_as_float(f2tf(f - __uint_as_float(hi)));
    }
}

// ============================================================================
// K1: h = x @ W (+ a_src, a_dst), 3xTF32 mma.
// CTA = 32 rows x 32 cols, 256 thr (8 warps = 2 row-groups x 4 col-blocks).
// Whole A tile loaded ONCE, row-contiguous (1600B streams -> DRAM-friendly),
// into 51.7KB dynamic smem (stride 404 = conflict-free frag LDS). B frags
// straight from L1-resident g_Whi/g_Wlo. Zero barriers in the k-loop.
// 3200 CTAs, 4 CTAs/SM for cross-CTA load/compute overlap.
// ============================================================================
#define TROWS 32
#define ASTR2 404
#define A_SMEM_BYTES (TROWS*ASTR2*4)   // 51712
__global__ __launch_bounds__(256) void k_gemm(
    const float* __restrict__ x,
    const float* __restrict__ att_src, const float* __restrict__ att_dst)
{
    extern __shared__ float shA[];               // [TROWS][ASTR2]
    __shared__ float shAS[TROWS][5], shAD[TROWS][5];

    const int t    = threadIdx.x;
    const int wid  = t >> 5;
    const int lane = t & 31;
    const int grp  = lane >> 2;                  // 0..7
    const int tig  = lane & 3;                   // 0..3
    const int rg   = wid >> 2;                   // row group 0..1 (16 rows)
    const int nq   = wid & 3;                    // col block 0..3 (8 cols)
    const size_t row0 = (size_t)blockIdx.x * TROWS;

    // ---- load full A tile, row-contiguous ----
    for (int i = t; i < TROWS * 100; i += 256) {
        int r = i / 100, pos = i - r * 100;      // 100 float4 per row
        cpa16(&shA[r * ASTR2 + pos * 4], x + (row0 + r) * INDIM + pos * 4);
    }
    cpa_commit();
    cpa_wait<0>();
    __syncthreads();

    // ---- k-loop: 50 x k8, no barriers ----
    float c0 = 0.f, c1 = 0.f, c2 = 0.f, c3 = 0.f;
    const int n = nq * 8 + grp;
    const float* Whn = g_Whi + n * INDIM;
    const float* Wln = g_Wlo + n * INDIM;
    const int abase = (rg * 16 + grp) * ASTR2 + tig;
#pragma unroll 5
    for (int k8 = 0; k8 < INDIM; k8 += 8) {
        int ab = abase + k8;
        float fa0 = shA[ab];
        float fa1 = shA[ab + 8 * ASTR2];
        float fa2 = shA[ab + 4];
        float fa3 = shA[ab + 8 * ASTR2 + 4];
        unsigned ah0 = f2tf(fa0), ah1 = f2tf(fa1);
        unsigned ah2 = f2tf(fa2), ah3 = f2tf(fa3);
        unsigned al0 = f2tf(fa0 - __uint_as_float(ah0));
        unsigned al1 = f2tf(fa1 - __uint_as_float(ah1));
        unsigned al2 = f2tf(fa2 - __uint_as_float(ah2));
        unsigned al3 = f2tf(fa3 - __uint_as_float(ah3));
        unsigned bh0 = __float_as_uint(Whn[k8 + tig]);
        unsigned bh1 = __float_as_uint(Whn[k8 + tig + 4]);
        unsigned bl0 = __float_as_uint(Wln[k8 + tig]);
        unsigned bl1 = __float_as_uint(Wln[k8 + tig + 4]);
        mma_tf32(c0, c1, c2, c3, ah0, ah1, ah2, ah3, bh0, bh1);
        mma_tf32(c0, c1, c2, c3, ah0, ah1, ah2, ah3, bl0, bl1);
        mma_tf32(c0, c1, c2, c3, al0, al1, al2, al3, bh0, bh1);
    }

    // ---- epilogue ----
    const int rA = rg * 16 + grp;                // tile-local rows
    const int rB = rA + 8;
    const int col = nq * 8 + 2 * tig;
    *(float2*)&g_h[(row0 + rA) * D1 + col] = make_float2(c0, c1);
    *(float2*)&g_h[(row0 + rB) * D1 + col] = make_float2(c2, c3);
    float s0 = att_src[col], s1 = att_src[col + 1];
    float d0 = att_dst[col], d1 = att_dst[col + 1];
    float asA = c0 * s0 + c1 * s1, adA = c0 * d0 + c1 * d1;
    float asB = c2 * s0 + c3 * s1, adB = c2 * d0 + c3 * d1;
#pragma unroll
    for (int d = 1; d <= 2; d <<= 1) {
        asA += __shfl_xor_sync(0xffffffffu, asA, d);
        adA += __shfl_xor_sync(0xffffffffu, adA, d);
        asB += __shfl_xor_sync(0xffffffffu, asB, d);
        adB += __shfl_xor_sync(0xffffffffu, adB, d);
    }
    if (tig == 0) {
        shAS[rA][nq] = asA; shAD[rA][nq] = adA;
        shAS[rB][nq] = asB; shAD[rB][nq] = adB;
    }
    __syncthreads();
    if (t < TROWS) {
        g_as[row0 + t] = shAS[t][0] + shAS[t][1] + shAS[t][2] + shAS[t][3];
        g_ad[row0 + t] = shAD[t][0] + shAD[t][1] + shAD[t][2] + shAD[t][3];
    }
}

// ============================================================================
// K2: per-graph GAT + TopK + MLP. Unchanged from round 9/11.
// ============================================================================
#define O_H    0        // 12800 f
#define O_SRC  12800    // 400*CAP u16 = 12800 words
#define O_CNT  25600    // 400 i
#define O_AS   26000    // 400 f
#define O_AD   26400    // 400 f
#define O_SV   26800    // 512 f
#define O_SI   27312    // 512 i
#define O_PM   12800    // alias
#define O_PS   13312
#define O_Z    13824
#define O_Z1   13888
#define O_Z2   13920
#define SMEM_WORDS 27824
#define SMEM_BYTES (SMEM_WORDS*4)

__global__ __launch_bounds__(512, 2) void k_graph(
    const void* __restrict__ edge_index,
    const float* __restrict__ gat_bias, const float* __restrict__ pool_w,
    const float* __restrict__ fc1_w, const float* __restrict__ fc1_b,
    const float* __restrict__ bn1_g, const float* __restrict__ bn1_b,
    const float* __restrict__ fc2_w, const float* __restrict__ fc2_b,
    const float* __restrict__ bn2_g, const float* __restrict__ bn2_b,
    const float* __restrict__ fc3_w, const float* __restrict__ fc3_b,
    float* __restrict__ out)
{
    extern __shared__ float sm[];
    float* sh_h   = sm + O_H;
    unsigned short* sh_src = (unsigned short*)(sm + O_SRC);
    int*   sh_cnt = (int*)(sm + O_CNT);
    float* sh_as  = sm + O_AS;
    float* sh_ad  = sm + O_AD;
    float* sh_sv  = sm + O_SV;
    int*   sh_si  = (int*)(sm + O_SI);
    float* sh_pm  = sm + O_PM;
    float* sh_ps  = sm + O_PS;
    float* sh_z   = sm + O_Z;
    float* sh_z1  = sm + O_Z1;
    float* sh_z2  = sm + O_Z2;

    const int b    = blockIdx.x;
    const int t    = threadIdx.x;
    const int lane = t & 31;
    const int w    = t >> 5;
    const int qu   = lane >> 3;
    const int ql   = lane & 7;
    const int base = b * G;
    const int is64 = detect_is64(edge_index);
    const long long e0 = (long long)b * EPG;
    const unsigned FULL = 0xffffffffu;

    {
        const float4* H4 = (const float4*)(g_h + (size_t)base * D1);
        float4* S4 = (float4*)sh_h;
        for (int i = t; i < G*D1/4; i += 512) cpa16(&S4[i], &H4[i]);
        cpa_commit();
        for (int i = t; i < G; i += 512) {
            sh_as[i] = g_as[base + i];
            sh_ad[i] = g_ad[base + i];
            sh_cnt[i] = 1;
            sh_src[i * CAP] = (unsigned short)i;
        }
    }
    __syncthreads();

    for (int i = t; i < EPG; i += 512) {
        int s = load_idx(edge_index, e0 + i, is64) - base;
        int d = load_idx(edge_index, ETOTLL + e0 + i, is64) - base;
        int p = atomicAdd(&sh_cnt[d], 1) & (CAP - 1);
        sh_src[d * CAP + p] = (unsigned short)s;
    }
    cpa_wait<0>();
    __syncthreads();

    {
        float pwl = pool_w[lane];
        float n2 = pwl * pwl;
#pragma unroll
        for (int d = 16; d >= 1; d >>= 1) n2 += __shfl_xor_sync(FULL, n2, d);
        float invn = rsqrtf(n2);
        float4 pw4 = *(const float4*)&pool_w[4*ql];
        float4 gb4 = *(const float4*)&gat_bias[4*ql];

        for (int vq = 4*w; vq < G; vq += 64) {
            int v = vq + qu;
            int s1 = sh_cnt[v]; if (s1 > CAP) s1 = CAP;
            float ad = sh_ad[v];
            const unsigned short* srcp = sh_src + v * CAP;
            u64t accA0 = 0ull, accB0 = 0ull, accA1 = 0ull, accB1 = 0ull;
            float denl = 0.f;
            int ncm = (s1 + 7) >> 3;
            ncm = max(ncm, __shfl_xor_sync(FULL, ncm, 8));
            ncm = max(ncm, __shfl_xor_sync(FULL, ncm, 16));
#pragma unroll 1
            for (int c = 0; c < ncm; ++c) {
                int i = (c << 3) + ql;
                float alpha = 0.f; int s = 0;
                if (i < s1) {
                    s = srcp[i];
                    float e = sh_as[s] + ad;
                    e = (e > 0.f) ? e : SLOPE * e;
                    alpha = __expf(e);
                }
                denl += alpha;
#pragma unroll
                for (int ii = 0; ii < 8; ii += 2) {
                    float a0 = __shfl_sync(FULL, alpha, ii,     8);
                    int  ss0 = __shfl_sync(FULL, s,     ii,     8);
                    float a1 = __shfl_sync(FULL, alpha, ii + 1, 8);
                    int  ss1 = __shfl_sync(FULL, s,     ii + 1, 8);
                    u64t a20 = pack2(a0, a0);
                    u64t a21 = pack2(a1, a1);
                    ulonglong2 hv0 = *(const ulonglong2*)&sh_h[(ss0 << 5) + (ql << 2)];
                    ulonglong2 hv1 = *(const ulonglong2*)&sh_h[(ss1 << 5) + (ql << 2)];
                    fma2(accA0, hv0.x, a20);
                    fma2(accB0, hv0.y, a20);
                    fma2(accA1, hv1.x, a21);
                    fma2(accB1, hv1.y, a21);
                }
            }
            const u64t ONE2 = pack2(1.f, 1.f);
            fma2(accA0, accA1, ONE2);
            fma2(accB0, accB1, ONE2);
            float den = denl;
            den += __shfl_xor_sync(FULL, den, 4, 8);
            den += __shfl_xor_sync(FULL, den, 2, 8);
            den += __shfl_xor_sync(FULL, den, 1, 8);
            float inv = 1.f / den;
            u64t i2 = pack2(inv, inv);
            u64t oA = pack2(gb4.x, gb4.y); fma2(oA, accA0, i2);
            u64t oB = pack2(gb4.z, gb4.w); fma2(oB, accB0, i2);
            float o0, o1, o2v, o3;
            unpack2(oA, o0, o1); unpack2(oB, o2v, o3);
            *(float4*)&g_out_buf[(size_t)(base + v) * D1 + (ql << 2)] =
                make_float4(o0, o1, o2v, o3);
            float p = o0*pw4.x + o1*pw4.y + o2v*pw4.z + o3*pw4.w;
            p += __shfl_xor_sync(FULL, p, 4, 8);
            p += __shfl_xor_sync(FULL, p, 2, 8);
            p += __shfl_xor_sync(FULL, p, 1, 8);
            if (ql == 0) {
                float sc = p * invn;
                sh_sv[v] = 1.f / (1.f + __expf(-sc));
                sh_si[v] = v;
            }
        }
    }
    if (t >= G) { sh_sv[t] = -1.f; sh_si[t] = t; }
    __syncthreads();

    for (int k = 2; k <= 512; k <<= 1) {
        for (int j = k >> 1; j > 0; j >>= 1) {
            int ixj = t ^ j;
            if (ixj > t) {
                float va = sh_sv[t], vb = sh_sv[ixj];
                int   ia = sh_si[t], ib = sh_si[ixj];
                bool before = (va > vb) || (va == vb && ia < ib);
                bool doswap = ((t & k) == 0) ? !before : before;
                if (doswap) {
                    sh_sv[t] = vb; sh_sv[ixj] = va;
                    sh_si[t] = ib; sh_si[ixj] = ia;
                }
            }
            __syncthreads();
        }
    }

    for (int i = t; i < KSEL; i += 512) {
        float v = sh_sv[i];
        out[OFF_SIG  + b * KSEL + i] = 1.f / (1.f + __expf(-v));
        out[OFF_PERM + b * KSEL + i] = (float)(sh_si[i] + base);
    }

    {
        float mx = -1e30f, smv = 0.f;
        for (int j = w; j < KSEL; j += 16) {
            float wt = sh_sv[j];
            float val = g_out_buf[(size_t)(base + sh_si[j]) * D1 + lane] * wt;
            mx = fmaxf(mx, val);
            smv += val;
        }
        sh_pm[w * 32 + lane] = mx;
        sh_ps[w * 32 + lane] = smv;
    }
    __syncthreads();
    if (t < D1) {
        float mx = -1e30f, smv = 0.f;
#pragma unroll
        for (int j = 0; j < 16; ++j) {
            mx = fmaxf(mx, sh_pm[j * 32 + t]);
            smv += sh_ps[j * 32 + t];
        }
        sh_z[t]      = mx;
        sh_z[D1 + t] = smv * (1.f / (float)KSEL);
    }
    __syncthreads();

    if (w == 0) {
        float acc = fc1_b[lane];
        for (int i = 0; i < 2*D1; ++i) acc += sh_z[i] * fc1_w[i * D1 + lane];
        acc = fmaxf(acc, 0.f);
        acc = acc * (bn1_g[lane] * BN_SCL) + bn1_b[lane];
        sh_z1[lane] = acc;
        __syncwarp();
        if (lane < 8) {
            float y = fc2_b[lane];
            for (int i = 0; i < D1; ++i) y += sh_z1[i] * fc2_w[i * 8 + lane];
            y = fmaxf(y, 0.f);
            y = y * (bn2_g[lane] * BN_SCL) + bn2_b[lane];
            sh_z2[lane] = y;
        }
        __syncwarp();
        if (lane < 2) {
            float y = fc3_b[lane];
            for (int i = 0; i < 8; ++i) y += sh_z2[i] * fc3_w[i * 2 + lane];
            float other = __shfl_xor_sync(0x3u, y, 1, 2);
            float m = fmaxf(y, other);
            float lse = m + logf(expf(y - m) + expf(other - m));
            out[b * 2 + lane] = y - lse;
        }
    }

    if (b == 0 && t < D1) out[OFF_POOLW + t] = pool_w[t];
}

// ============================================================================
extern "C" void kernel_launch(void* const* d_in, const int* in_sizes, int n_in,
                              void* d_out, int out_size)
{
    const float* x        = (const float*)d_in[0];
    const void*  edge_idx = d_in[1];
    const float* W        = (const float*)d_in[4];
    const float* att_src  = (const float*)d_in[5];
    const float* att_dst  = (const float*)d_in[6];
    const float* gat_bias = (const float*)d_in[7];
    const float* pool_w   = (const float*)d_in[8];
    const float* fc1_w    = (const float*)d_in[9];
    const float* fc1_b    = (const float*)d_in[10];
    const float* bn1_g    = (const float*)d_in[11];
    const float* bn1_b    = (const float*)d_in[12];
    const float* fc2_w    = (const float*)d_in[13];
    const float* fc2_b    = (const float*)d_in[14];
    const float* bn2_g    = (const float*)d_in[15];
    const float* bn2_b    = (const float*)d_in[16];
    const float* fc3_w    = (const float*)d_in[17];
    const float* fc3_b    = (const float*)d_in[18];
    float* out = (float*)d_out;

    cudaFuncSetAttribute(k_gemm, cudaFuncAttributeMaxDynamicSharedMemorySize,
                         A_SMEM_BYTES);
    cudaFuncSetAttribute(k_graph, cudaFuncAttributeMaxDynamicSharedMemorySize,
                         SMEM_BYTES);

    k_prep<<<(INDIM*D1 + 255)/256, 256>>>(W);
    k_gemm<<<NN/TROWS, 256, A_SMEM_BYTES>>>(x, att_src, att_dst);
    k_graph<<<NB, 512, SMEM_BYTES>>>(edge_idx, gat_bias, pool_w,
                                     fc1_w, fc1_b, bn1_g, bn1_b,
                                     fc2_w, fc2_b, bn2_g, bn2_b,
                                     fc3_w, fc3_b, out);
}

// round 15
// speedup vs baseline: 1.6548x; 1.6548x over previous
#include <cuda_runtime.h>
#include <math.h>

// ---------------- problem constants ----------------
#define NB     256                 // graphs per batch
#define G      400                 // nodes per graph
#define DEG    32                  // avg degree
#define INDIM  400
#define D1     32
#define KSEL   200                 // top-k kept nodes
#define EPG    (G*DEG)             // 12800 edges per graph
#define NN     (NB*G)              // 102400 nodes
#define ETOTLL ((long long)NB*(long long)EPG)  // 3276800 edges
#define SLOPE  0.2f
#define BN_SCL 0.99999499987f      // 1/sqrt(1+1e-5)
#define CAP    64                  // per-dst bin capacity

// output layout (float32): logits[NB*2] | pool_w[32] | sig(vals)[NB*K] | perm[NB*K]
#define OFF_POOLW (NB*2)               // 512
#define OFF_SIG   (OFF_POOLW + D1)     // 544
#define OFF_PERM  (OFF_SIG + NB*KSEL)  // 51744

// ---------------- scratch (module-static, no runtime alloc) ----------------
__device__ float g_h[(size_t)NN*D1];     // 13.1 MB
__device__ float g_out_buf[(size_t)NN*D1];
__device__ float g_as[NN];
__device__ float g_ad[NN];

// ---------------- index dtype handling ----------------
__device__ __forceinline__ int detect_is64(const void* p) {
    const int* w = (const int*)p;
    int any = 0;
#pragma unroll
    for (int j = 1; j <= 15; j += 2) any |= w[j];
    return any == 0;
}
__device__ __forceinline__ int load_idx(const void* p, long long i, int is64) {
    return is64 ? (int)((const long long*)p)[i] : ((const int*)p)[i];
}

// ---------------- f32x2 / cp.async / mma helpers ----------------
typedef unsigned long long u64t;
__device__ __forceinline__ void fma2(u64t& d, u64t a, u64t b) {
    asm volatile("fma.rn.f32x2 %0, %1, %2, %0;" : "+l"(d) : "l"(a), "l"(b));
}
__device__ __forceinline__ u64t pack2(float lo, float hi) {
    u64t r;
    asm("mov.b64 %0, {%1, %2};" : "=l"(r) : "f"(lo), "f"(hi));
    return r;
}
__device__ __forceinline__ void unpack2(u64t v, float& lo, float& hi) {
    asm("mov.b64 {%0, %1}, %2;" : "=f"(lo), "=f"(hi) : "l"(v));
}
__device__ __forceinline__ void cpa16(void* s, const void* g) {
    unsigned sa = (unsigned)__cvta_generic_to_shared(s);
    asm volatile("cp.async.cg.shared.global [%0], [%1], 16;" :: "r"(sa), "l"(g));
}
__device__ __forceinline__ void cpa_commit() {
    asm volatile("cp.async.commit_group;");
}
template <int N> __device__ __forceinline__ void cpa_wait() {
    asm volatile("cp.async.wait_group %0;" :: "n"(N));
}
__device__ __forceinline__ unsigned f2tf(float f) {
    unsigned u;
    asm("cvt.rna.tf32.f32 %0, %1;" : "=r"(u) : "f"(f));
    return u;
}
__device__ __forceinline__ void mma_tf32(
    float& c0, float& c1, float& c2, float& c3,
    unsigned a0, unsigned a1, unsigned a2, unsigned a3,
    unsigned b0, unsigned b1)
{
    asm volatile(
        "mma.sync.aligned.m16n8k8.row.col.f32.tf32.tf32.f32 "
        "{%0,%1,%2,%3}, {%4,%5,%6,%7}, {%8,%9}, {%0,%1,%2,%3};"
        : "+f"(c0), "+f"(c1), "+f"(c2), "+f"(c3)
        : "r"(a0), "r"(a1), "r"(a2), "r"(a3), "r"(b0), "r"(b1));
}

// ============================================================================
// K1: h = x @ W (+ a_src, a_dst) via 3xTF32 mma (hi/lo error compensation).
// 3-stage ring, 2-chunk lookahead. RACE FIX vs round 13: a barrier BEFORE the
// stage writes (buffer (cc+2)%3 was consumed at iter cc-1; the pre-write
// barrier orders that consumption before reuse). cpa_wait<2> now waits on a
// chunk issued 2 iterations earlier -> no DRAM-latency block.
// ============================================================================
#define KC    16
#define AST   20                   // A row stride (words) within a k-chunk
#define NST   3                    // pipeline stages
#define NCHNK (INDIM/KC)           // 25
__global__ __launch_bounds__(256) void k_gemm(
    const float* __restrict__ x, const float* __restrict__ W,
    const float* __restrict__ att_src, const float* __restrict__ att_dst)
{
    __shared__ float shA [NST][128*AST];   // 3 x 10.0 KB
    __shared__ float shBh[NST][32*AST];    // 3 x 2.5 KB
    __shared__ float shBl[NST][32*AST];    // 3 x 2.5 KB

    const int t    = threadIdx.x;
    const int wid  = t >> 5;
    const int lane = t & 31;
    const int grp  = lane >> 2;          // 0..7
    const int tig  = lane & 3;           // 0..3
    const size_t row0 = (size_t)blockIdx.x * 128;
    const int wr0 = wid * 16;            // warp's first row in tile

    float c[4][4];
#pragma unroll
    for (int nt = 0; nt < 4; ++nt)
#pragma unroll
        for (int i = 0; i < 4; ++i) c[nt][i] = 0.f;

    // A loader mapping: float4 index i in [0,512): r=i>>2, ks=(i&3)*4
    // W loader mapping: n=t&31, kk=t>>5 and kk+8
    const int wn = t & 31, wk = t >> 5;

    auto issueA = [&](int cg, int sb) {
        const float* xs = x + (size_t)cg * KC;
#pragma unroll
        for (int j = 0; j < 2; ++j) {
            int i = t + j*256;
            int r = i >> 2, ks = (i & 3) * 4;
            cpa16(&shA[sb][r*AST + ks], xs + (row0 + r)*INDIM + ks);
        }
        cpa_commit();
    };
    auto stageB = [&](int cg, int sb) {
#pragma unroll
        for (int j = 0; j < 2; ++j) {
            int kk = wk + j*8;
            float f = W[(cg*KC + kk)*32 + wn];
            unsigned hi = f2tf(f);
            float lof = f - __uint_as_float(hi);
            shBh[sb][wn*AST + kk] = __uint_as_float(hi);
            shBl[sb][wn*AST + kk] = __uint_as_float(f2tf(lof));
        }
    };

    // ---- prologue: chunks 0 and 1 ----
    issueA(0, 0); stageB(0, 0);
    issueA(1, 1); stageB(1, 1);

    int sb = 0;                          // buffer of chunk cc
#pragma unroll 1
    for (int cc = 0; cc < NCHNK; ++cc) {
        if (cc + 2 < NCHNK) {
            int nb = sb + 2; if (nb >= NST) nb -= NST;
            __syncthreads();             // all warps done consuming chunk cc-1
            issueA(cc + 2, nb);
            stageB(cc + 2, nb);
            cpa_wait<2>();               // chunk cc (issued 2 iters ago) done
        } else if (cc + 1 < NCHNK) {
            cpa_wait<1>();
        } else {
            cpa_wait<0>();
        }
        __syncthreads();

        const float* A  = shA[sb];
        const float* Bh = shBh[sb];
        const float* Bl = shBl[sb];
#pragma unroll
        for (int k8 = 0; k8 < KC; k8 += 8) {
            int ab = (wr0 + grp)*AST + tig + k8;
            float fa0 = A[ab];
            float fa1 = A[ab + 8*AST];
            float fa2 = A[ab + 4];
            float fa3 = A[ab + 8*AST + 4];
            unsigned ah0 = f2tf(fa0), ah1 = f2tf(fa1);
            unsigned ah2 = f2tf(fa2), ah3 = f2tf(fa3);
            unsigned al0 = f2tf(fa0 - __uint_as_float(ah0));
            unsigned al1 = f2tf(fa1 - __uint_as_float(ah1));
            unsigned al2 = f2tf(fa2 - __uint_as_float(ah2));
            unsigned al3 = f2tf(fa3 - __uint_as_float(ah3));
#pragma unroll
            for (int nt = 0; nt < 4; ++nt) {
                int bb = (nt*8 + grp)*AST + tig + k8;
                unsigned bh0 = __float_as_uint(Bh[bb]);
                unsigned bh1 = __float_as_uint(Bh[bb + 4]);
                unsigned bl0 = __float_as_uint(Bl[bb]);
                unsigned bl1 = __float_as_uint(Bl[bb + 4]);
                mma_tf32(c[nt][0], c[nt][1], c[nt][2], c[nt][3],
                         ah0, ah1, ah2, ah3, bh0, bh1);
                mma_tf32(c[nt][0], c[nt][1], c[nt][2], c[nt][3],
                         ah0, ah1, ah2, ah3, bl0, bl1);
                mma_tf32(c[nt][0], c[nt][1], c[nt][2], c[nt][3],
                         al0, al1, al2, al3, bh0, bh1);
            }
        }
        ++sb; if (sb >= NST) sb -= NST;
    }

    // ---- epilogue: store h rows, per-row a_src/a_dst ----
    size_t ra = row0 + wr0 + grp;
    size_t rb = ra + 8;
    float asA = 0.f, adA = 0.f, asB = 0.f, adB = 0.f;
#pragma unroll
    for (int nt = 0; nt < 4; ++nt) {
        int col = nt*8 + 2*tig;
        *(float2*)&g_h[ra*D1 + col] = make_float2(c[nt][0], c[nt][1]);
        *(float2*)&g_h[rb*D1 + col] = make_float2(c[nt][2], c[nt][3]);
        float s0 = att_src[col], s1 = att_src[col+1];
        float d0 = att_dst[col], d1 = att_dst[col+1];
        asA += c[nt][0]*s0 + c[nt][1]*s1;
        adA += c[nt][0]*d0 + c[nt][1]*d1;
        asB += c[nt][2]*s0 + c[nt][3]*s1;
        adB += c[nt][2]*d0 + c[nt][3]*d1;
    }
#pragma unroll
    for (int d = 1; d <= 2; d <<= 1) {
        asA += __shfl_xor_sync(0xffffffffu, asA, d);
        adA += __shfl_xor_sync(0xffffffffu, adA, d);
        asB += __shfl_xor_sync(0xffffffffu, asB, d);
        adB += __shfl_xor_sync(0xffffffffu, adB, d);
    }
    if (tig == 0) {
        g_as[ra] = asA; g_ad[ra] = adA;
        g_as[rb] = asB; g_ad[rb] = adB;
    }
}

// ============================================================================
// K2: per-graph GAT + TopK + MLP. Unchanged from round 9/11.
// ============================================================================
#define O_H    0        // 12800 f
#define O_SRC  12800    // 400*CAP u16 = 12800 words
#define O_CNT  25600    // 400 i
#define O_AS   26000    // 400 f
#define O_AD   26400    // 400 f
#define O_SV   26800    // 512 f
#define O_SI   27312    // 512 i
#define O_PM   12800    // alias
#define O_PS   13312
#define O_Z    13824
#define O_Z1   13888
#define O_Z2   13920
#define SMEM_WORDS 27824
#define SMEM_BYTES (SMEM_WORDS*4)

__global__ __launch_bounds__(512, 2) void k_graph(
    const void* __restrict__ edge_index,
    const float* __restrict__ gat_bias, const float* __restrict__ pool_w,
    const float* __restrict__ fc1_w, const float* __restrict__ fc1_b,
    const float* __restrict__ bn1_g, const float* __restrict__ bn1_b,
    const float* __restrict__ fc2_w, const float* __restrict__ fc2_b,
    const float* __restrict__ bn2_g, const float* __restrict__ bn2_b,
    const float* __restrict__ fc3_w, const float* __restrict__ fc3_b,
    float* __restrict__ out)
{
    extern __shared__ float sm[];
    float* sh_h   = sm + O_H;
    unsigned short* sh_src = (unsigned short*)(sm + O_SRC);
    int*   sh_cnt = (int*)(sm + O_CNT);
    float* sh_as  = sm + O_AS;
    float* sh_ad  = sm + O_AD;
    float* sh_sv  = sm + O_SV;
    int*   sh_si  = (int*)(sm + O_SI);
    float* sh_pm  = sm + O_PM;
    float* sh_ps  = sm + O_PS;
    float* sh_z   = sm + O_Z;
    float* sh_z1  = sm + O_Z1;
    float* sh_z2  = sm + O_Z2;

    const int b    = blockIdx.x;
    const int t    = threadIdx.x;
    const int lane = t & 31;
    const int w    = t >> 5;
    const int qu   = lane >> 3;
    const int ql   = lane & 7;
    const int base = b * G;
    const int is64 = detect_is64(edge_index);
    const long long e0 = (long long)b * EPG;
    const unsigned FULL = 0xffffffffu;

    {
        const float4* H4 = (const float4*)(g_h + (size_t)base * D1);
        float4* S4 = (float4*)sh_h;
        for (int i = t; i < G*D1/4; i += 512) cpa16(&S4[i], &H4[i]);
        cpa_commit();
        for (int i = t; i < G; i += 512) {
            sh_as[i] = g_as[base + i];
            sh_ad[i] = g_ad[base + i];
            sh_cnt[i] = 1;
            sh_src[i * CAP] = (unsigned short)i;
        }
    }
    __syncthreads();

    for (int i = t; i < EPG; i += 512) {
        int s = load_idx(edge_index, e0 + i, is64) - base;
        int d = load_idx(edge_index, ETOTLL + e0 + i, is64) - base;
        int p = atomicAdd(&sh_cnt[d], 1) & (CAP - 1);
        sh_src[d * CAP + p] = (unsigned short)s;
    }
    cpa_wait<0>();
    __syncthreads();

    {
        float pwl = pool_w[lane];
        float n2 = pwl * pwl;
#pragma unroll
        for (int d = 16; d >= 1; d >>= 1) n2 += __shfl_xor_sync(FULL, n2, d);
        float invn = rsqrtf(n2);
        float4 pw4 = *(const float4*)&pool_w[4*ql];
        float4 gb4 = *(const float4*)&gat_bias[4*ql];

        for (int vq = 4*w; vq < G; vq += 64) {
            int v = vq + qu;
            int s1 = sh_cnt[v]; if (s1 > CAP) s1 = CAP;
            float ad = sh_ad[v];
            const unsigned short* srcp = sh_src + v * CAP;
            u64t accA0 = 0ull, accB0 = 0ull, accA1 = 0ull, accB1 = 0ull;
            float denl = 0.f;
            int ncm = (s1 + 7) >> 3;
            ncm = max(ncm, __shfl_xor_sync(FULL, ncm, 8));
            ncm = max(ncm, __shfl_xor_sync(FULL, ncm, 16));
#pragma unroll 1
            for (int c = 0; c < ncm; ++c) {
                int i = (c << 3) + ql;
                float alpha = 0.f; int s = 0;
                if (i < s1) {
                    s = srcp[i];
                    float e = sh_as[s] + ad;
                    e = (e > 0.f) ? e : SLOPE * e;
                    alpha = __expf(e);
                }
                denl += alpha;
#pragma unroll
                for (int ii = 0; ii < 8; ii += 2) {
                    float a0 = __shfl_sync(FULL, alpha, ii,     8);
                    int  ss0 = __shfl_sync(FULL, s,     ii,     8);
                    float a1 = __shfl_sync(FULL, alpha, ii + 1, 8);
                    int  ss1 = __shfl_sync(FULL, s,     ii + 1, 8);
                    u64t a20 = pack2(a0, a0);
                    u64t a21 = pack2(a1, a1);
                    ulonglong2 hv0 = *(const ulonglong2*)&sh_h[(ss0 << 5) + (ql << 2)];
                    ulonglong2 hv1 = *(const ulonglong2*)&sh_h[(ss1 << 5) + (ql << 2)];
                    fma2(accA0, hv0.x, a20);
                    fma2(accB0, hv0.y, a20);
                    fma2(accA1, hv1.x, a21);
                    fma2(accB1, hv1.y, a21);
                }
            }
            const u64t ONE2 = pack2(1.f, 1.f);
            fma2(accA0, accA1, ONE2);
            fma2(accB0, accB1, ONE2);
            float den = denl;
            den += __shfl_xor_sync(FULL, den, 4, 8);
            den += __shfl_xor_sync(FULL, den, 2, 8);
            den += __shfl_xor_sync(FULL, den, 1, 8);
            float inv = 1.f / den;
            u64t i2 = pack2(inv, inv);
            u64t oA = pack2(gb4.x, gb4.y); fma2(oA, accA0, i2);
            u64t oB = pack2(gb4.z, gb4.w); fma2(oB, accB0, i2);
            float o0, o1, o2v, o3;
            unpack2(oA, o0, o1); unpack2(oB, o2v, o3);
            *(float4*)&g_out_buf[(size_t)(base + v) * D1 + (ql << 2)] =
                make_float4(o0, o1, o2v, o3);
            float p = o0*pw4.x + o1*pw4.y + o2v*pw4.z + o3*pw4.w;
            p += __shfl_xor_sync(FULL, p, 4, 8);
            p += __shfl_xor_sync(FULL, p, 2, 8);
            p += __shfl_xor_sync(FULL, p, 1, 8);
            if (ql == 0) {
                float sc = p * invn;
                sh_sv[v] = 1.f / (1.f + __expf(-sc));
                sh_si[v] = v;
            }
        }
    }
    if (t >= G) { sh_sv[t] = -1.f; sh_si[t] = t; }
    __syncthreads();

    for (int k = 2; k <= 512; k <<= 1) {
        for (int j = k >> 1; j > 0; j >>= 1) {
            int ixj = t ^ j;
            if (ixj > t) {
                float va = sh_sv[t], vb = sh_sv[ixj];
                int   ia = sh_si[t], ib = sh_si[ixj];
                bool before = (va > vb) || (va == vb && ia < ib);
                bool doswap = ((t & k) == 0) ? !before : before;
                if (doswap) {
                    sh_sv[t] = vb; sh_sv[ixj] = va;
                    sh_si[t] = ib; sh_si[ixj] = ia;
                }
            }
            __syncthreads();
        }
    }

    for (int i = t; i < KSEL; i += 512) {
        float v = sh_sv[i];
        out[OFF_SIG  + b * KSEL + i] = 1.f / (1.f + __expf(-v));
        out[OFF_PERM + b * KSEL + i] = (float)(sh_si[i] + base);
    }

    {
        float mx = -1e30f, smv = 0.f;
        for (int j = w; j < KSEL; j += 16) {
            float wt = sh_sv[j];
            float val = g_out_buf[(size_t)(base + sh_si[j]) * D1 + lane] * wt;
            mx = fmaxf(mx, val);
            smv += val;
        }
        sh_pm[w * 32 + lane] = mx;
        sh_ps[w * 32 + lane] = smv;
    }
    __syncthreads();
    if (t < D1) {
        float mx = -1e30f, smv = 0.f;
#pragma unroll
        for (int j = 0; j < 16; ++j) {
            mx = fmaxf(mx, sh_pm[j * 32 + t]);
            smv += sh_ps[j * 32 + t];
        }
        sh_z[t]      = mx;
        sh_z[D1 + t] = smv * (1.f / (float)KSEL);
    }
    __syncthreads();

    if (w == 0) {
        float acc = fc1_b[lane];
        for (int i = 0; i < 2*D1; ++i) acc += sh_z[i] * fc1_w[i * D1 + lane];
        acc = fmaxf(acc, 0.f);
        acc = acc * (bn1_g[lane] * BN_SCL) + bn1_b[lane];
        sh_z1[lane] = acc;
        __syncwarp();
        if (lane < 8) {
            float y = fc2_b[lane];
            for (int i = 0; i < D1; ++i) y += sh_z1[i] * fc2_w[i * 8 + lane];
            y = fmaxf(y, 0.f);
            y = y * (bn2_g[lane] * BN_SCL) + bn2_b[lane];
            sh_z2[lane] = y;
        }
        __syncwarp();
        if (lane < 2) {
            float y = fc3_b[lane];
            for (int i = 0; i < 8; ++i) y += sh_z2[i] * fc3_w[i * 2 + lane];
            float other = __shfl_xor_sync(0x3u, y, 1, 2);
            float m = fmaxf(y, other);
            float lse = m + logf(expf(y - m) + expf(other - m));
            out[b * 2 + lane] = y - lse;
        }
    }

    if (b == 0 && t < D1) out[OFF_POOLW + t] = pool_w[t];
}

// ============================================================================
extern "C" void kernel_launch(void* const* d_in, const int* in_sizes, int n_in,
                              void* d_out, int out_size)
{
    const float* x        = (const float*)d_in[0];
    const void*  edge_idx = d_in[1];
    const float* W        = (const float*)d_in[4];
    const float* att_src  = (const float*)d_in[5];
    const float* att_dst  = (const float*)d_in[6];
    const float* gat_bias = (const float*)d_in[7];
    const float* pool_w   = (const float*)d_in[8];
    const float* fc1_w    = (const float*)d_in[9];
    const float* fc1_b    = (const float*)d_in[10];
    const float* bn1_g    = (const float*)d_in[11];
    const float* bn1_b    = (const float*)d_in[12];
    const float* fc2_w    = (const float*)d_in[13];
    const float* fc2_b    = (const float*)d_in[14];
    const float* bn2_g    = (const float*)d_in[15];
    const float* bn2_b    = (const float*)d_in[16];
    const float* fc3_w    = (const float*)d_in[17];
    const float* fc3_b    = (const float*)d_in[18];
    float* out = (float*)d_out;

    cudaFuncSetAttribute(k_graph, cudaFuncAttributeMaxDynamicSharedMemorySize,
                         SMEM_BYTES);

    k_gemm<<<NN/128, 256>>>(x, W, att_src, att_dst);
    k_graph<<<NB, 512, SMEM_BYTES>>>(edge_idx, gat_bias, pool_w,
                                     fc1_w, fc1_b, bn1_g, bn1_b,
                                     fc2_w, fc2_b, bn2_g, bn2_b,
                                     fc3_w, fc3_b, out);
}